// round 8
// baseline (speedup 1.0000x reference)
#include <cuda_runtime.h>

// Staggered parallel transport, 8 paths, 32^4 lattice — fused single kernel,
// per-warp SMEM staging of U matrices (coalesced LDG, low register pressure).
//
// Layouts (row-major, metadata order):
//   d_in[0] x_re : (8, V, 3) float    d_in[1] x_im : (8, V, 3)
//   d_in[2] U_re : (4, V, 9) float    d_in[3] U_im : (4, V, 9)
//   d_out        : (2, 8, V, 3) float   (re block then im block)
// site s = ((x*32 + y)*32 + z)*32 + t
//
// Channels:
//   0: copy            1: fwd mu=0       2: fwd mu=1   3: fwd mu=2
//   4: fwd mu=3        5: bwd mu=0 (scatter)   6: bwd mu=1 (scatter)
//   7: fwd mu=0 then fwd mu=1  — first hop in SMEM (y-tiled block + halo)
//
// Block = 256 threads = (t:32, y:8) at fixed (x,z); warp <-> one t-line.
// Each warp's 32 sites own 288 contiguous floats of each U array; staging
// turns the stride-36B per-thread U reads into 9 coalesced 128B LDGs.

#define VOL (32 * 32 * 32 * 32)

// mv: y = sgn * U v   (U read from smem, row-major per-site layout)
__device__ __forceinline__ void mv(const float* Ur, const float* Ui,
                                   const float* vr, const float* vi,
                                   float sgn, float* yr, float* yi) {
#pragma unroll
    for (int a = 0; a < 3; a++) {
        float sr = 0.f, si = 0.f;
#pragma unroll
        for (int b = 0; b < 3; b++) {
            float ur = Ur[a * 3 + b], ui = Ui[a * 3 + b];
            sr = fmaf(ur, vr[b], sr);
            sr = fmaf(-ui, vi[b], sr);
            si = fmaf(ur, vi[b], si);
            si = fmaf(ui, vr[b], si);
        }
        yr[a] = sgn * sr;
        yi[a] = sgn * si;
    }
}

// mvdag: y = sgn * U^dag v
__device__ __forceinline__ void mvdag(const float* Ur, const float* Ui,
                                      const float* vr, const float* vi,
                                      float sgn, float* yr, float* yi) {
#pragma unroll
    for (int a = 0; a < 3; a++) {
        float sr = 0.f, si = 0.f;
#pragma unroll
        for (int b = 0; b < 3; b++) {
            float ur = Ur[b * 3 + a], ui = Ui[b * 3 + a];  // conj-transpose
            sr = fmaf(ur, vr[b], sr);
            sr = fmaf(ui, vi[b], sr);
            si = fmaf(ur, vi[b], si);
            si = fmaf(-ui, vr[b], si);
        }
        yr[a] = sgn * sr;
        yi[a] = sgn * si;
    }
}

__device__ __forceinline__ void ldv(const float* __restrict__ xr,
                                    const float* __restrict__ xi,
                                    int ch, int s, float* vr, float* vi) {
    int b = (ch * VOL + s) * 3;
#pragma unroll
    for (int c = 0; c < 3; c++) {
        vr[c] = __ldg(xr + b + c);
        vi[c] = __ldg(xi + b + c);
    }
}

__device__ __forceinline__ void stv(float* __restrict__ out, int ch, int s,
                                    const float* yr, const float* yi) {
    int br = (ch * VOL + s) * 3;
    int bi = ((8 + ch) * VOL + s) * 3;
#pragma unroll
    for (int c = 0; c < 3; c++) {
        out[br + c] = yr[c];
        out[bi + c] = yi[c];
    }
}

// Coalesced per-warp U staging: 288 contiguous floats (32 sites x 9) re + im.
// sline = site index of lane 0 of this warp's t-line.
__device__ __forceinline__ void stageU(const float* __restrict__ Ur,
                                       const float* __restrict__ Ui,
                                       int mu, int sline, int lid,
                                       float* bR, float* bI) {
    int b = (mu * VOL + sline) * 9;
#pragma unroll
    for (int k = 0; k < 9; k++) {
        bR[k * 32 + lid] = __ldg(Ur + b + k * 32 + lid);
        bI[k * 32 + lid] = __ldg(Ui + b + k * 32 + lid);
    }
}

__global__ void __launch_bounds__(256, 4)
k_fused(const float* __restrict__ xr, const float* __restrict__ xi,
        const float* __restrict__ Ur, const float* __restrict__ Ui,
        float* __restrict__ out) {
    // ch7 intermediate: [component 0..5][y-row 0..8][t]
    __shared__ float tmp_s[6][9][32];
    // per-warp U staging buffers (reused across the 4 U sections)
    __shared__ float uSr[8][288];
    __shared__ float uSi[8][288];

    int tid = threadIdx.x;
    int t = tid & 31;
    int yl = tid >> 5;            // warp index == local y-row, 0..7

    int bid = blockIdx.x;         // 0..4095
    int y0 = (bid & 3) << 3;      // {0,8,16,24}
    int z = (bid >> 2) & 31;
    int x = bid >> 7;

    int y = y0 + yl;
    int s = (x << 15) | (y << 10) | (z << 5) | t;
    int sline = s & ~31;          // lane-0 site of this warp's t-line

    int s_px = (s & ~(31 << 15)) | (((x + 1) & 31) << 15);
    int s_py = (s & ~(31 << 10)) | (((y + 1) & 31) << 10);
    int s_pz = (s & ~(31 << 5)) | (((z + 1) & 31) << 5);
    int s_pt = (s & ~31) | ((t + 1) & 31);

    float eta1 = (x & 1) ? -1.f : 1.f;            // (-1)^x
    float eta2 = ((x ^ y) & 1) ? -1.f : 1.f;      // (-1)^(x+y)
    float eta3 = ((x ^ y ^ z) & 1) ? -1.f : 1.f;  // (-1)^(x+y+z)

    float* bR = uSr[yl];
    float* bI = uSi[yl];
    const float* ur = bR + t * 9;   // this thread's U in smem
    const float* ui = bI + t * 9;

    float vr[3], vi[3], yr[3], yi[3];

    // ---- mu = 0 section: U0 serves ch1, ch5, ch7-hop1 ----
    stageU(Ur, Ui, 0, sline, t, bR, bI);
    __syncwarp();

    // ch1: out1(s) = U0(s) x1(s + x_hat)       (eta0 = 1)
    ldv(xr, xi, 1, s_px, vr, vi);
    mv(ur, ui, vr, vi, 1.f, yr, yi);
    stv(out, 1, s, yr, yi);

    // ch5 (scatter): out5(s + x_hat) = U0^dag(s) x5(s)
    ldv(xr, xi, 5, s, vr, vi);
    mvdag(ur, ui, vr, vi, 1.f, yr, yi);
    stv(out, 5, s_px, yr, yi);

    // ch7 hop 1 -> smem: tmp(s) = U0(s) x7(s + x_hat)
    ldv(xr, xi, 7, s_px, vr, vi);
    mv(ur, ui, vr, vi, 1.f, yr, yi);
#pragma unroll
    for (int c = 0; c < 3; c++) {
        tmp_s[c][yl][t] = yr[c];
        tmp_s[3 + c][yl][t] = yi[c];
    }
    __syncwarp();

    // halo row y0+8 (warp 0 only; warp-uniform branch)
    if (yl == 0) {
        int yh = (y0 + 8) & 31;
        int shl = (x << 15) | (yh << 10) | (z << 5);     // halo t-line base
        int sh = shl | t;
        int sh_px = (sh & ~(31 << 15)) | (((x + 1) & 31) << 15);
        stageU(Ur, Ui, 0, shl, t, bR, bI);
        __syncwarp();
        ldv(xr, xi, 7, sh_px, vr, vi);
        mv(ur, ui, vr, vi, 1.f, yr, yi);
#pragma unroll
        for (int c = 0; c < 3; c++) {
            tmp_s[c][8][t] = yr[c];
            tmp_s[3 + c][8][t] = yi[c];
        }
        __syncwarp();
    }

    // ch0: identity copy
    ldv(xr, xi, 0, s, vr, vi);
    stv(out, 0, s, vr, vi);

    // ---- mu = 2 section: ch3 ----
    stageU(Ur, Ui, 2, sline, t, bR, bI);
    __syncwarp();
    ldv(xr, xi, 3, s_pz, vr, vi);
    mv(ur, ui, vr, vi, eta2, yr, yi);
    stv(out, 3, s, yr, yi);
    __syncwarp();

    // ---- mu = 3 section: ch4 ----
    stageU(Ur, Ui, 3, sline, t, bR, bI);
    __syncwarp();
    ldv(xr, xi, 4, s_pt, vr, vi);
    mv(ur, ui, vr, vi, eta3, yr, yi);
    stv(out, 4, s, yr, yi);

    __syncthreads();  // tmp_s complete block-wide; also fences buffer reuse

    // ---- mu = 1 section: U1 serves ch2, ch6, ch7-final ----
    stageU(Ur, Ui, 1, sline, t, bR, bI);
    __syncwarp();

    // ch2: out2(s) = eta1(s) U1(s) x2(s + y_hat)
    ldv(xr, xi, 2, s_py, vr, vi);
    mv(ur, ui, vr, vi, eta1, yr, yi);
    stv(out, 2, s, yr, yi);

    // ch6 (scatter): out6(s + y_hat) = eta1(s) U1^dag(s) x6(s)
    ldv(xr, xi, 6, s, vr, vi);
    mvdag(ur, ui, vr, vi, eta1, yr, yi);
    stv(out, 6, s_py, yr, yi);

    // ch7: out7(s) = eta1(s) U1(s) tmp(s + y_hat)   [smem]
#pragma unroll
    for (int c = 0; c < 3; c++) {
        vr[c] = tmp_s[c][yl + 1][t];
        vi[c] = tmp_s[3 + c][yl + 1][t];
    }
    mv(ur, ui, vr, vi, eta1, yr, yi);
    stv(out, 7, s, yr, yi);
}

extern "C" void kernel_launch(void* const* d_in, const int* in_sizes, int n_in,
                              void* d_out, int out_size) {
    const float* xr = (const float*)d_in[0];
    const float* xi = (const float*)d_in[1];
    const float* Ur = (const float*)d_in[2];
    const float* Ui = (const float*)d_in[3];
    float* out = (float*)d_out;

    k_fused<<<4096, 256>>>(xr, xi, Ur, Ui, out);
}

// round 9
// speedup vs baseline: 1.1747x; 1.1747x over previous
#include <cuda_runtime.h>

// Staggered parallel transport, 8 paths, 32^4 lattice — fused single kernel.
// R6 structure (register-resident U, smem only for ch7 intermediate) with
// __launch_bounds__(256,4) to cap regs at 64 -> 4 CTAs/SM.
//
// Layouts (row-major, metadata order):
//   d_in[0] x_re : (8, V, 3) float    d_in[1] x_im : (8, V, 3)
//   d_in[2] U_re : (4, V, 9) float    d_in[3] U_im : (4, V, 9)
//   d_out        : (2, 8, V, 3) float   (re block then im block)
// site s = ((x*32 + y)*32 + z)*32 + t
//
// Channels:
//   0: copy            1: fwd mu=0       2: fwd mu=1   3: fwd mu=2
//   4: fwd mu=3        5: bwd mu=0 (scatter)   6: bwd mu=1 (scatter)
//   7: fwd mu=0 then fwd mu=1  — first hop in SMEM (y-tiled block + halo)
//
// Block = 256 threads = (t:32, y:8) at fixed (x, z).

#define VOL (32 * 32 * 32 * 32)

__device__ __forceinline__ void mv(const float* __restrict__ Ur,
                                   const float* __restrict__ Ui,
                                   const float* vr, const float* vi,
                                   float sgn, float* yr, float* yi) {
#pragma unroll
    for (int a = 0; a < 3; a++) {
        float sr = 0.f, si = 0.f;
#pragma unroll
        for (int b = 0; b < 3; b++) {
            float ur = Ur[a * 3 + b], ui = Ui[a * 3 + b];
            sr = fmaf(ur, vr[b], sr);
            sr = fmaf(-ui, vi[b], sr);
            si = fmaf(ur, vi[b], si);
            si = fmaf(ui, vr[b], si);
        }
        yr[a] = sgn * sr;
        yi[a] = sgn * si;
    }
}

__device__ __forceinline__ void mvdag(const float* __restrict__ Ur,
                                      const float* __restrict__ Ui,
                                      const float* vr, const float* vi,
                                      float sgn, float* yr, float* yi) {
#pragma unroll
    for (int a = 0; a < 3; a++) {
        float sr = 0.f, si = 0.f;
#pragma unroll
        for (int b = 0; b < 3; b++) {
            float ur = Ur[b * 3 + a], ui = Ui[b * 3 + a];  // conj-transpose
            sr = fmaf(ur, vr[b], sr);
            sr = fmaf(ui, vi[b], sr);
            si = fmaf(ur, vi[b], si);
            si = fmaf(-ui, vr[b], si);
        }
        yr[a] = sgn * sr;
        yi[a] = sgn * si;
    }
}

__device__ __forceinline__ void ldv(const float* __restrict__ xr,
                                    const float* __restrict__ xi,
                                    int ch, int s, float* vr, float* vi) {
    int b = (ch * VOL + s) * 3;
#pragma unroll
    for (int c = 0; c < 3; c++) {
        vr[c] = __ldg(xr + b + c);
        vi[c] = __ldg(xi + b + c);
    }
}

__device__ __forceinline__ void ldU(const float* __restrict__ Ur,
                                    const float* __restrict__ Ui,
                                    int mu, int s, float* ur, float* ui) {
    int b = (mu * VOL + s) * 9;
#pragma unroll
    for (int k = 0; k < 9; k++) {
        ur[k] = __ldg(Ur + b + k);
        ui[k] = __ldg(Ui + b + k);
    }
}

__device__ __forceinline__ void stv(float* __restrict__ out, int ch, int s,
                                    const float* yr, const float* yi) {
    int br = (ch * VOL + s) * 3;
    int bi = ((8 + ch) * VOL + s) * 3;
#pragma unroll
    for (int c = 0; c < 3; c++) {
        out[br + c] = yr[c];
        out[bi + c] = yi[c];
    }
}

__global__ void __launch_bounds__(256, 4)
k_fused(const float* __restrict__ xr, const float* __restrict__ xi,
        const float* __restrict__ Ur, const float* __restrict__ Ui,
        float* __restrict__ out) {
    // smem tmp for ch7 first hop: [component 0..5][y-row 0..8][t]
    __shared__ float tmp_s[6][9][32];

    int tid = threadIdx.x;
    int t = tid & 31;
    int yl = tid >> 5;            // 0..7

    int bid = blockIdx.x;         // 0..4095
    int y0 = (bid & 3) << 3;      // {0,8,16,24}
    int z = (bid >> 2) & 31;
    int x = bid >> 7;

    int y = y0 + yl;
    int s = (x << 15) | (y << 10) | (z << 5) | t;

    int s_px = (s & ~(31 << 15)) | (((x + 1) & 31) << 15);
    int s_py = (s & ~(31 << 10)) | (((y + 1) & 31) << 10);
    int s_pz = (s & ~(31 << 5)) | (((z + 1) & 31) << 5);
    int s_pt = (s & ~31) | ((t + 1) & 31);

    float eta1 = (x & 1) ? -1.f : 1.f;            // (-1)^x
    float eta2 = ((x ^ y) & 1) ? -1.f : 1.f;      // (-1)^(x+y)
    float eta3 = ((x ^ y ^ z) & 1) ? -1.f : 1.f;  // (-1)^(x+y+z)

    float vr[3], vi[3], yr[3], yi[3];

    // ch0: identity copy (hoisted: short live range, kicks off early MLP)
    ldv(xr, xi, 0, s, vr, vi);
    stv(out, 0, s, vr, vi);

    // ---- mu = 0 block: U0(s) serves ch1, ch5, and the ch7 first hop ----
    {
        float U0r[9], U0i[9];
        ldU(Ur, Ui, 0, s, U0r, U0i);

        // ch1: out1(s) = U0(s) x1(s + x_hat)       (eta0 = 1)
        ldv(xr, xi, 1, s_px, vr, vi);
        mv(U0r, U0i, vr, vi, 1.f, yr, yi);
        stv(out, 1, s, yr, yi);

        // ch5 (scatter): out5(s + x_hat) = U0^dag(s) x5(s)
        ldv(xr, xi, 5, s, vr, vi);
        mvdag(U0r, U0i, vr, vi, 1.f, yr, yi);
        stv(out, 5, s_px, yr, yi);

        // ch7 first hop -> smem: tmp(s) = U0(s) x7(s + x_hat)
        ldv(xr, xi, 7, s_px, vr, vi);
        mv(U0r, U0i, vr, vi, 1.f, yr, yi);
#pragma unroll
        for (int c = 0; c < 3; c++) {
            tmp_s[c][yl][t] = yr[c];
            tmp_s[3 + c][yl][t] = yi[c];
        }

        // halo row y0+8 (one warp, reuses U0 register arrays)
        if (yl == 0) {
            int yh = (y0 + 8) & 31;
            int sh = (x << 15) | (yh << 10) | (z << 5) | t;
            int sh_px = (sh & ~(31 << 15)) | (((x + 1) & 31) << 15);
            ldU(Ur, Ui, 0, sh, U0r, U0i);
            ldv(xr, xi, 7, sh_px, vr, vi);
            mv(U0r, U0i, vr, vi, 1.f, yr, yi);
#pragma unroll
            for (int c = 0; c < 3; c++) {
                tmp_s[c][8][t] = yr[c];
                tmp_s[3 + c][8][t] = yi[c];
            }
        }
    }

    // ---- mu = 2: ch3 ----
    {
        float U2r[9], U2i[9];
        ldU(Ur, Ui, 2, s, U2r, U2i);
        ldv(xr, xi, 3, s_pz, vr, vi);
        mv(U2r, U2i, vr, vi, eta2, yr, yi);
        stv(out, 3, s, yr, yi);
    }

    // ---- mu = 3: ch4 ----
    {
        float U3r[9], U3i[9];
        ldU(Ur, Ui, 3, s, U3r, U3i);
        ldv(xr, xi, 4, s_pt, vr, vi);
        mv(U3r, U3i, vr, vi, eta3, yr, yi);
        stv(out, 4, s, yr, yi);
    }

    __syncthreads();

    // ---- mu = 1 block: U1(s) serves ch2, ch6, ch7 second hop ----
    {
        float U1r[9], U1i[9];
        ldU(Ur, Ui, 1, s, U1r, U1i);

        // ch2: out2(s) = eta1(s) U1(s) x2(s + y_hat)
        ldv(xr, xi, 2, s_py, vr, vi);
        mv(U1r, U1i, vr, vi, eta1, yr, yi);
        stv(out, 2, s, yr, yi);

        // ch6 (scatter): out6(s + y_hat) = eta1(s) U1^dag(s) x6(s)
        ldv(xr, xi, 6, s, vr, vi);
        mvdag(U1r, U1i, vr, vi, eta1, yr, yi);
        stv(out, 6, s_py, yr, yi);

        // ch7: out7(s) = eta1(s) U1(s) tmp(s + y_hat)   [smem]
#pragma unroll
        for (int c = 0; c < 3; c++) {
            vr[c] = tmp_s[c][yl + 1][t];
            vi[c] = tmp_s[3 + c][yl + 1][t];
        }
        mv(U1r, U1i, vr, vi, eta1, yr, yi);
        stv(out, 7, s, yr, yi);
    }
}

extern "C" void kernel_launch(void* const* d_in, const int* in_sizes, int n_in,
                              void* d_out, int out_size) {
    const float* xr = (const float*)d_in[0];
    const float* xi = (const float*)d_in[1];
    const float* Ur = (const float*)d_in[2];
    const float* Ui = (const float*)d_in[3];
    float* out = (float*)d_out;

    k_fused<<<4096, 256>>>(xr, xi, Ur, Ui, out);
}